// round 9
// baseline (speedup 1.0000x reference)
#include <cuda_runtime.h>

#define NQ    20
#define NPART 10
#define NB    512          // blocks; 2 columns each, 8-warp octet per column
#define CPB   2
#define TPB   512          // 16 warps

__device__ __forceinline__ float2 cmul(float2 a, float2 b) {
    return make_float2(a.x * b.x - a.y * b.y, a.x * b.y + a.y * b.x);
}
__device__ __forceinline__ float2 cadd(float2 a, float2 b) {
    return make_float2(a.x + b.x, a.y + b.y);
}

// full 2x2 complex butterfly (scalar FFMA form)
__device__ __forceinline__ void bfly(float2& A0, float2& A1,
                                     float2 V00, float2 V01, float2 V10, float2 V11) {
    float2 a0 = A0, a1 = A1;
    A0 = cadd(cmul(V00, a0), cmul(V01, a1));
    A1 = cadd(cmul(V10, a0), cmul(V11, a1));
}

// Exchange address bijection on 0..1023. Bank bits (ad[4:0]) =
// (h6^h7, h5^h0, h4^h1, h3, h2); high bits = (h9,h8,h7,h1,h0).
// Conflict-free for BOTH the store pattern (lane spans h[6:2]) and the
// read/epilogue pattern (lane spans h7,h[3:0]).
__device__ __forceinline__ int xad(int h) {
    int b4 = ((h >> 6) ^ (h >> 7)) & 1;
    int b3 = ((h >> 5) ^  h      ) & 1;
    int b2 = ((h >> 4) ^ (h >> 1)) & 1;
    int low = (b4 << 4) | (b3 << 3) | (b2 << 2) | (((h >> 3) & 1) << 1) | ((h >> 2) & 1);
    int hi  = (((h >> 7) & 7) << 2) | ((h >> 1) & 1) << 1 | (h & 1);
    return (hi << 5) | low;
}

// ---------------------------------------------------------------------------
// 512 blocks x 512 threads; each 8-warp OCTET owns one column l.
// 4 float2 amps/thread, h = (ow<<7)|(lane<<2)|r:
//   2 reg stages (h bits 0-1, gates 9,8)
//   5 shfl stages (h bits 2-6 = lane bits, gates 7,6,5,4,3)
//   swizzled smem exchange -> new h = r'<<8 | (lane&1)<<7 | ow<<4 | lane>>1
//   1 shfl stage (h bit 7 = lane bit 0, gate 2)
//   2 reg stages (h bits 8,9, gates 1,0)
// |amp|^2 -> block reduce over 2 columns -> RED.F32 atomicAdd into out.
// ---------------------------------------------------------------------------
__global__ void __launch_bounds__(TPB, 3) sim_kernel(const float* __restrict__ x,
                                                     const float* __restrict__ w,
                                                     float* __restrict__ out) {
    extern __shared__ float dynf[];
    // overlay: T1/T2 tables (16 KB) live only until synthesis; staging
    // planes (2 columns x re/im x 1024 floats = 16 KB) after.
    float2* sT1 = (float2*)dynf;            // [1024]
    float2* sT2 = (float2*)dynf + 1024;     // [1024]

    __shared__ float2 sv[NQ][2];
    __shared__ int    sFB[NQ];
    __shared__ float2 sV[40];
    __shared__ int    sXR[4];

    const int tid  = threadIdx.x;
    const int warp = tid >> 5;
    const int lane = tid & 31;
    const int c    = warp >> 3;        // column slot 0..1
    const int ow   = warp & 7;         // warp-in-octet (h bits 7,8,9 pre-exchange contribution 7..9? -> bits 7,8,9 of h as ow bits 0..2)

    const float RS2  = 0.70710678118654752440f;   // 1/sqrt(2)
    const float WMUL = 0.63245553203367586640f;   // sqrt(2/5)

    if (tid < NQ) {
        // encoding column v_q = Rz(atan(x^2)) * Ry(atan(x)) * H |0>
        const int q = tid;
        float xq = x[q];
        float th = atanf(xq);
        float cc, ss;
        sincosf(0.5f * th, &ss, &cc);
        float a = (cc - ss) * RS2;
        float b = (cc + ss) * RS2;
        float ph = 0.5f * atanf(xq * xq);
        float pc, ps;
        sincosf(ph, &ps, &pc);
        sv[q][0] = make_float2(a * pc, -a * ps);
        sv[q][1] = make_float2(b * pc,  b * ps);

        // f = inverse CNOT-ring permutation on basis bit p=tid
        int y = 1 << tid;
        for (int qq = NQ - 1; qq >= 0; --qq) {
            int cb  = 19 - qq;
            int tb2 = 19 - ((qq + 2) % NQ);
            int tb1 = 19 - ((qq + 1) % NQ);
            if ((y >> cb) & 1) y ^= (1 << tb2);
            if ((y >> cb) & 1) y ^= (1 << tb1);
        }
        sFB[tid] = y;
    }

    if (tid < NPART) {
        // fused variational gate V = Rx(w2) * Rz(w1) * Rx(w0), measured qubits
        const int q = tid;
        float w0 = w[3 * q + 0] * WMUL;
        float w1 = w[3 * q + 1] * WMUL;
        float w2 = w[3 * q + 2] * WMUL;
        float c0, s0, c1, s1, c2, s2;
        sincosf(0.5f * w0, &s0, &c0);
        sincosf(0.5f * w1, &s1, &c1);
        sincosf(0.5f * w2, &s2, &c2);
        float2 r00 = make_float2(c0, 0.f), r01 = make_float2(0.f, -s0);
        float2 d0  = make_float2(c1, -s1), d1  = make_float2(c1,  s1);
        float2 A00 = cmul(d0, r00), A01 = cmul(d0, r01);
        float2 A10 = cmul(d1, r01), A11 = cmul(d1, r00);
        float2 m = make_float2(0.f, -s2);
        sV[4 * q + 0] = cadd(make_float2(c2 * A00.x, c2 * A00.y), cmul(m, A10));
        sV[4 * q + 1] = cadd(make_float2(c2 * A01.x, c2 * A01.y), cmul(m, A11));
        sV[4 * q + 2] = cadd(cmul(m, A00), make_float2(c2 * A10.x, c2 * A10.y));
        sV[4 * q + 3] = cadd(cmul(m, A01), make_float2(c2 * A11.x, c2 * A11.y));
    }
    __syncthreads();

    // product tables (2 entries/thread)
#pragma unroll
    for (int a = tid; a < 1024; a += TPB) {
        float2 p1 = make_float2(1.f, 0.f);
        float2 p2 = make_float2(1.f, 0.f);
#pragma unroll
        for (int q = 0; q < NPART; ++q)
            p1 = cmul(p1, sv[q][(a >> (9 - q)) & 1]);
#pragma unroll
        for (int q = NPART; q < NQ; ++q)
            p2 = cmul(p2, sv[q][(a >> (19 - q)) & 1]);
        sT1[a] = p1;
        sT2[a] = p2;
    }
    if (tid < 4) {
        int v = 0;
        if (tid & 1) v ^= sFB[10];   // h bit 0 -> global bit 10
        if (tid & 2) v ^= sFB[11];   // h bit 1 -> global bit 11
        sXR[tid] = v;
    }
    __syncthreads();

    // ---- this octet's column
    const int l = blockIdx.x * CPB + c;
    int xl = 0;
#pragma unroll
    for (int j = 0; j < 10; ++j)
        if ((l >> j) & 1) xl ^= sFB[j];
    int hx = 0;
#pragma unroll
    for (int p = 0; p < 5; ++p)
        if ((lane >> p) & 1) hx ^= sFB[12 + p];   // h bit 2+p -> global bit 12+p
    if (ow & 1) hx ^= sFB[17];                    // h bit 7
    if (ow & 2) hx ^= sFB[18];                    // h bit 8
    if (ow & 4) hx ^= sFB[19];                    // h bit 9
    const int xbase = xl ^ hx;

    // synthesize 4 amps: h = (ow<<7)|(lane<<2)|r
    float2 a[4];
#pragma unroll
    for (int r = 0; r < 4; ++r) {
        int xx = xbase ^ sXR[r];
        a[r] = cmul(sT1[xx >> 10], sT2[xx & 1023]);
    }
    __syncthreads();   // all warps done reading tables -> staging may overwrite

    // phase A: 2 register stages on h bits 0,1 (gates 9, 8)
    {
        float2 V00 = sV[36], V01 = sV[37], V10 = sV[38], V11 = sV[39]; // gate 9
        bfly(a[0], a[1], V00, V01, V10, V11);
        bfly(a[2], a[3], V00, V01, V10, V11);
    }
    {
        float2 V00 = sV[32], V01 = sV[33], V10 = sV[34], V11 = sV[35]; // gate 8
        bfly(a[0], a[2], V00, V01, V10, V11);
        bfly(a[1], a[3], V00, V01, V10, V11);
    }

    // phase B: 5 shfl stages on h bits 2..6 (lane bit p, gates 7..3)
#pragma unroll
    for (int p = 0; p < 5; ++p) {
        const int q = 7 - p;
        float2 V00 = sV[4 * q + 0], V01 = sV[4 * q + 1];
        float2 V10 = sV[4 * q + 2], V11 = sV[4 * q + 3];
        const int bitv = (lane >> p) & 1;
        const float2 Vs = bitv ? V11 : V00;
        const float2 Vo = bitv ? V10 : V01;
#pragma unroll
        for (int r = 0; r < 4; ++r) {
            float2 o;
            o.x = __shfl_xor_sync(0xffffffffu, a[r].x, 1 << p);
            o.y = __shfl_xor_sync(0xffffffffu, a[r].y, 1 << p);
            a[r] = cadd(cmul(Vs, a[r]), cmul(Vo, o));
        }
    }

    // phase C: exchange through swizzled re/im planes
    float* sRe = dynf + c * 2048;
    float* sIm = sRe + 1024;
#pragma unroll
    for (int r = 0; r < 4; ++r) {
        int ad = xad((ow << 7) | (lane << 2) | r);
        sRe[ad] = a[r].x;
        sIm[ad] = a[r].y;
    }
    asm volatile("bar.sync %0, %1;" :: "r"(c + 1), "r"(256) : "memory");

    // new mapping: h = (r<<8) | (lane&1)<<7 | (ow<<4) | (lane>>1)
    const int nbase = ((lane & 1) << 7) | (ow << 4) | (lane >> 1);
#pragma unroll
    for (int r = 0; r < 4; ++r) {
        int ad = xad((r << 8) | nbase);
        a[r] = make_float2(sRe[ad], sIm[ad]);
    }

    // phase D: 1 shfl stage on h bit 7 (lane bit 0, gate 2)
    {
        float2 V00 = sV[8], V01 = sV[9], V10 = sV[10], V11 = sV[11];
        const int bitv = lane & 1;
        const float2 Vs = bitv ? V11 : V00;
        const float2 Vo = bitv ? V10 : V01;
#pragma unroll
        for (int r = 0; r < 4; ++r) {
            float2 o;
            o.x = __shfl_xor_sync(0xffffffffu, a[r].x, 1);
            o.y = __shfl_xor_sync(0xffffffffu, a[r].y, 1);
            a[r] = cadd(cmul(Vs, a[r]), cmul(Vo, o));
        }
    }

    // phase E: 2 register stages on h bits 8 (gate 1), 9 (gate 0)
    {
        float2 V00 = sV[4], V01 = sV[5], V10 = sV[6], V11 = sV[7];     // gate 1
        bfly(a[0], a[1], V00, V01, V10, V11);
        bfly(a[2], a[3], V00, V01, V10, V11);
    }
    {
        float2 V00 = sV[0], V01 = sV[1], V10 = sV[2], V11 = sV[3];     // gate 0
        bfly(a[0], a[2], V00, V01, V10, V11);
        bfly(a[1], a[3], V00, V01, V10, V11);
    }

    // |amp|^2 back to this thread's own addresses (same set it read)
#pragma unroll
    for (int r = 0; r < 4; ++r) {
        int ad = xad((r << 8) | nbase);
        sRe[ad] = a[r].x * a[r].x + a[r].y * a[r].y;
    }
    __syncthreads();

    // block reduce over the 2 columns; iterate h with lane spanning h[6:2]
    // (store pattern -> conflict-free), rotate start by block to spread L2.
#pragma unroll
    for (int i = 0; i < 2; ++i) {
        int t = tid + i * TPB;                       // 0..1023
        int h = ((t & 31) << 2) | ((t >> 5) & 3) | (((t >> 7) & 7) << 7);
        int ad = xad(h);
        float s = dynf[ad] + dynf[2048 + ad];
        atomicAdd(&out[h], s);
    }
}

extern "C" void kernel_launch(void* const* d_in, const int* in_sizes, int n_in,
                              void* d_out, int out_size) {
    const float* x = (const float*)d_in[0];   // (1, 20) float32
    const float* w = (const float*)d_in[1];   // (60,)  float32
    float* out = (float*)d_out;               // (1, 1024) float32

    cudaMemsetAsync(out, 0, 1024 * sizeof(float));
    const int dynsmem = CPB * 2048 * 4;       // 16 KB (tables overlay staging)
    cudaFuncSetAttribute(sim_kernel, cudaFuncAttributeMaxDynamicSharedMemorySize, dynsmem);
    sim_kernel<<<NB, TPB, dynsmem>>>(x, w, out);
}

// round 10
// speedup vs baseline: 2.1868x; 2.1868x over previous
#include <cuda_runtime.h>

#define NQ    20
#define NPART 10
#define NB    147          // blocks; 7 columns each, 4-warp quad per column
#define CPB   7
#define TPB   (CPB * 128)  // 896 threads = 28 warps

__device__ __forceinline__ float2 cmul(float2 a, float2 b) {
    return make_float2(a.x * b.x - a.y * b.y, a.x * b.y + a.y * b.x);
}
__device__ __forceinline__ float2 cadd(float2 a, float2 b) {
    return make_float2(a.x + b.x, a.y + b.y);
}

// full 2x2 complex butterfly (scalar FFMA form)
__device__ __forceinline__ void bfly(float2& A0, float2& A1,
                                     float2 V00, float2 V01, float2 V10, float2 V11) {
    float2 a0 = A0, a1 = A1;
    A0 = cadd(cmul(V00, a0), cmul(V01, a1));
    A1 = cadd(cmul(V10, a0), cmul(V11, a1));
}

// bank-conflict-free bijection on 0..1023: XOR h[7:3] into h[4:0]
__device__ __forceinline__ int swz(int h) {
    return h ^ ((h >> 3) & 31);
}

// ---------------------------------------------------------------------------
// 147 blocks x 896 threads; each 4-warp QUAD owns one column l (7/block).
// 8 float2 amps/thread, h = (qw<<8)|(lane<<3)|r:
//   3 reg stages (h bits 0-2, gates 9,8,7)
//   5 shfl stages (h bits 3-7 = lane bits, gates 6,5,4,3,2)
//   swizzled smem exchange -> h bits 8,9 into register bits
//   2 reg stages (gates 1,0)
// |amp|^2 (zero-weighted for dummy columns) -> block reduce over 7 columns
// -> RED.F32 atomicAdd into out.
// ---------------------------------------------------------------------------
__global__ void __launch_bounds__(TPB, 1) sim_kernel(const float* __restrict__ x,
                                                     const float* __restrict__ w,
                                                     float* __restrict__ out) {
    extern __shared__ float dynf[];
    // overlay: T1/T2 tables (16 KB) live only until synthesis; staging
    // planes (7 columns x re/im x 1024 floats = 56 KB) after.
    float2* sT1 = (float2*)dynf;            // [1024]
    float2* sT2 = (float2*)dynf + 1024;     // [1024]

    __shared__ float2 sv[NQ][2];
    __shared__ int    sFB[NQ];
    __shared__ float2 sV[40];
    __shared__ int    sXR[8];

    const int tid  = threadIdx.x;
    const int warp = tid >> 5;
    const int lane = tid & 31;
    const int c    = warp >> 2;        // column slot 0..6
    const int qw   = warp & 3;         // warp-in-quad (h bits 8,9)

    const float RS2  = 0.70710678118654752440f;   // 1/sqrt(2)
    const float WMUL = 0.63245553203367586640f;   // sqrt(2/5)

    if (tid < NQ) {
        // encoding column v_q = Rz(atan(x^2)) * Ry(atan(x)) * H |0>
        const int q = tid;
        float xq = x[q];
        float th = atanf(xq);
        float cc, ss;
        sincosf(0.5f * th, &ss, &cc);
        float a = (cc - ss) * RS2;
        float b = (cc + ss) * RS2;
        float ph = 0.5f * atanf(xq * xq);
        float pc, ps;
        sincosf(ph, &ps, &pc);
        sv[q][0] = make_float2(a * pc, -a * ps);
        sv[q][1] = make_float2(b * pc,  b * ps);

        // f = inverse CNOT-ring permutation on basis bit p=tid
        int y = 1 << tid;
        for (int qq = NQ - 1; qq >= 0; --qq) {
            int cb  = 19 - qq;
            int tb2 = 19 - ((qq + 2) % NQ);
            int tb1 = 19 - ((qq + 1) % NQ);
            if ((y >> cb) & 1) y ^= (1 << tb2);
            if ((y >> cb) & 1) y ^= (1 << tb1);
        }
        sFB[tid] = y;
    }

    if (tid < NPART) {
        // fused variational gate V = Rx(w2) * Rz(w1) * Rx(w0), measured qubits
        const int q = tid;
        float w0 = w[3 * q + 0] * WMUL;
        float w1 = w[3 * q + 1] * WMUL;
        float w2 = w[3 * q + 2] * WMUL;
        float c0, s0, c1, s1, c2, s2;
        sincosf(0.5f * w0, &s0, &c0);
        sincosf(0.5f * w1, &s1, &c1);
        sincosf(0.5f * w2, &s2, &c2);
        float2 r00 = make_float2(c0, 0.f), r01 = make_float2(0.f, -s0);
        float2 d0  = make_float2(c1, -s1), d1  = make_float2(c1,  s1);
        float2 A00 = cmul(d0, r00), A01 = cmul(d0, r01);
        float2 A10 = cmul(d1, r01), A11 = cmul(d1, r00);
        float2 m = make_float2(0.f, -s2);
        sV[4 * q + 0] = cadd(make_float2(c2 * A00.x, c2 * A00.y), cmul(m, A10));
        sV[4 * q + 1] = cadd(make_float2(c2 * A01.x, c2 * A01.y), cmul(m, A11));
        sV[4 * q + 2] = cadd(cmul(m, A00), make_float2(c2 * A10.x, c2 * A10.y));
        sV[4 * q + 3] = cadd(cmul(m, A01), make_float2(c2 * A11.x, c2 * A11.y));
    }
    __syncthreads();

    // product tables
    for (int a = tid; a < 1024; a += TPB) {
        float2 p1 = make_float2(1.f, 0.f);
        float2 p2 = make_float2(1.f, 0.f);
#pragma unroll
        for (int q = 0; q < NPART; ++q)
            p1 = cmul(p1, sv[q][(a >> (9 - q)) & 1]);
#pragma unroll
        for (int q = NPART; q < NQ; ++q)
            p2 = cmul(p2, sv[q][(a >> (19 - q)) & 1]);
        sT1[a] = p1;
        sT2[a] = p2;
    }
    if (tid < 8) {
        int v = 0;
#pragma unroll
        for (int i = 0; i < 3; ++i)
            if ((tid >> i) & 1) v ^= sFB[10 + i];   // h bit i -> global bit 10+i
        sXR[tid] = v;
    }
    __syncthreads();

    // ---- this quad's column (dummy slots masked via wgt)
    const int lraw = blockIdx.x * CPB + c;
    const float wgt = (lraw < 1024) ? 1.f : 0.f;
    const int l = lraw & 1023;
    int xl = 0;
#pragma unroll
    for (int j = 0; j < 10; ++j)
        if ((l >> j) & 1) xl ^= sFB[j];
    int hx = 0;
#pragma unroll
    for (int p = 0; p < 5; ++p)
        if ((lane >> p) & 1) hx ^= sFB[13 + p];   // h bit 3+p -> global bit 13+p
    if (qw & 1) hx ^= sFB[18];                    // h bit 8
    if (qw & 2) hx ^= sFB[19];                    // h bit 9
    const int xbase = xl ^ hx;

    // synthesize 8 amps: h = (qw<<8)|(lane<<3)|r
    float2 a[8];
#pragma unroll
    for (int r = 0; r < 8; ++r) {
        int xx = xbase ^ sXR[r];
        a[r] = cmul(sT1[xx >> 10], sT2[xx & 1023]);
    }
    __syncthreads();   // all warps done reading tables -> staging may overwrite

    // phase 1: 3 register stages on h bits 0..2 (gates q = 9,8,7)
#pragma unroll
    for (int b = 0; b < 3; ++b) {
        const int q = 9 - b;
        float2 V00 = sV[4 * q + 0], V01 = sV[4 * q + 1];
        float2 V10 = sV[4 * q + 2], V11 = sV[4 * q + 3];
#pragma unroll
        for (int g = 0; g < 4; ++g) {
            int lo = g & ((1 << b) - 1);
            int r0 = ((g >> b) << (b + 1)) | lo;
            int r1 = r0 | (1 << b);
            bfly(a[r0], a[r1], V00, V01, V10, V11);
        }
    }

    // phase 2: 5 shfl stages on h bits 3..7 (lane bit p, gates q = 6..2)
#pragma unroll
    for (int p = 0; p < 5; ++p) {
        const int q = 6 - p;
        float2 V00 = sV[4 * q + 0], V01 = sV[4 * q + 1];
        float2 V10 = sV[4 * q + 2], V11 = sV[4 * q + 3];
        const int bitv = (lane >> p) & 1;
        const float2 Vs = bitv ? V11 : V00;
        const float2 Vo = bitv ? V10 : V01;
#pragma unroll
        for (int r = 0; r < 8; ++r) {
            float2 o;
            o.x = __shfl_xor_sync(0xffffffffu, a[r].x, 1 << p);
            o.y = __shfl_xor_sync(0xffffffffu, a[r].y, 1 << p);
            a[r] = cadd(cmul(Vs, a[r]), cmul(Vo, o));
        }
    }

    // exchange: bring h bits 8,9 into register bits (swizzled planes)
    float* sRe = dynf + c * 2048;
    float* sIm = sRe + 1024;
#pragma unroll
    for (int r = 0; r < 8; ++r) {
        int ad = swz((qw << 8) | (lane << 3) | r);
        sRe[ad] = a[r].x;
        sIm[ad] = a[r].y;
    }
    asm volatile("bar.sync %0, %1;" :: "r"(c + 1), "r"(128) : "memory");

    // new mapping: h = (r'&3)<<8 | lane<<3 | qw<<1 | (r'>>2)
#pragma unroll
    for (int r = 0; r < 8; ++r) {
        int h = ((r & 3) << 8) | (lane << 3) | (qw << 1) | (r >> 2);
        int ad = swz(h);
        a[r] = make_float2(sRe[ad], sIm[ad]);
    }

    // phase 3: 2 register stages on h bit 8 (gate 1, r' bit0), h bit 9 (gate 0, r' bit1)
    {
        float2 V00 = sV[4], V01 = sV[5], V10 = sV[6], V11 = sV[7];     // gate 1
        bfly(a[0], a[1], V00, V01, V10, V11);
        bfly(a[2], a[3], V00, V01, V10, V11);
        bfly(a[4], a[5], V00, V01, V10, V11);
        bfly(a[6], a[7], V00, V01, V10, V11);
    }
    {
        float2 V00 = sV[0], V01 = sV[1], V10 = sV[2], V11 = sV[3];     // gate 0
        bfly(a[0], a[2], V00, V01, V10, V11);
        bfly(a[1], a[3], V00, V01, V10, V11);
        bfly(a[4], a[6], V00, V01, V10, V11);
        bfly(a[5], a[7], V00, V01, V10, V11);
    }

    // |amp|^2 back to the same swizzled addresses this thread read
    // (dummy columns weighted to zero)
#pragma unroll
    for (int r = 0; r < 8; ++r) {
        int h = ((r & 3) << 8) | (lane << 3) | (qw << 1) | (r >> 2);
        sRe[swz(h)] = wgt * (a[r].x * a[r].x + a[r].y * a[r].y);
    }
    __syncthreads();

    // block reduce over the 7 columns, RED.F32 into out (order-insensitive
    // to ~1e-7; tolerance is 1e-3)
    for (int h = tid; h < 1024; h += TPB) {
        const int ad = swz(h);
        float s = 0.f;
#pragma unroll
        for (int cc = 0; cc < CPB; ++cc)
            s += dynf[cc * 2048 + ad];
        atomicAdd(&out[h], s);
    }
}

extern "C" void kernel_launch(void* const* d_in, const int* in_sizes, int n_in,
                              void* d_out, int out_size) {
    const float* x = (const float*)d_in[0];   // (1, 20) float32
    const float* w = (const float*)d_in[1];   // (60,)  float32
    float* out = (float*)d_out;               // (1, 1024) float32

    cudaMemsetAsync(out, 0, 1024 * sizeof(float));
    const int dynsmem = CPB * 2048 * 4;       // 56 KB (tables overlay staging)
    cudaFuncSetAttribute(sim_kernel, cudaFuncAttributeMaxDynamicSharedMemorySize, dynsmem);
    sim_kernel<<<NB, TPB, dynsmem>>>(x, w, out);
}